// round 1
// baseline (speedup 1.0000x reference)
#include <cuda_runtime.h>
#include <cstdint>

// ---------------------------------------------------------------------------
// Problem constants (fixed shapes for this problem instance)
// ---------------------------------------------------------------------------
#define DX      16
#define DY      8
#define MR      64
#define MBAR    256
#define NT      9
#define GOUT    64
#define HX      1024
#define EX_DIM  512
#define HRNN    512
#define HB      2048
#define TOTAL   2049            // (NT-1)*MBAR + 1
#define M_TOTAL 16640           // (MR + 1) * MBAR : group 0 = base, 1..64 = displaced

// GEMM tiling
#define BM 128
#define BN 64
#define BK 16

// ---------------------------------------------------------------------------
// Scratch (no allocations allowed -> __device__ globals)
// ---------------------------------------------------------------------------
__device__ float g_eY[HRNN];
__device__ float g_bb1eff[HB];
__device__ float g_H1[M_TOTAL * HX];        // 68 MB
__device__ float g_EX[M_TOTAL * EX_DIM];    // 34 MB
__device__ float g_H2[M_TOTAL * HB];        // 136 MB
__device__ float g_OUT[M_TOTAL * GOUT];     // 4.3 MB
__device__ float g_partial[MR * GOUT];

// Robustly read a small scalar that may be stored as int32 or float32.
__device__ __forceinline__ int read_int(const int* p) {
    int v = *p;
    if (v >= 0 && v < (1 << 20)) return v;
    return (int)__int_as_float(v);
}

// ---------------------------------------------------------------------------
// RNN: eY = final carry of 7-step tanh RNN over Y[q, k+1:, :]
// Single CTA, 512 threads (one per hidden unit).
// ---------------------------------------------------------------------------
__global__ void rnn_kernel(const float* __restrict__ Y,
                           const float* __restrict__ Wih,
                           const float* __restrict__ Whh,
                           const float* __restrict__ bh,
                           const int* kptr, const int* qptr) {
    __shared__ float h[HRNN];
    __shared__ float hn[HRNN];
    int i = threadIdx.x;
    int k = read_int(kptr), q = read_int(qptr);
    h[i] = 0.f;
    __syncthreads();
    int steps = NT - (k + 1);
    for (int s = 0; s < steps; s++) {
        const float* y = Y + ((size_t)q * NT + (k + 1 + s)) * DY;
        float acc = bh[i];
#pragma unroll
        for (int d = 0; d < DY; d++) acc += y[d] * Wih[d * HRNN + i];
#pragma unroll 8
        for (int kk = 0; kk < HRNN; kk++) acc += h[kk] * Whh[kk * HRNN + i];
        hn[i] = tanhf(acc);
        __syncthreads();
        h[i] = hn[i];
        __syncthreads();
    }
    g_eY[i] = h[i];
}

// ---------------------------------------------------------------------------
// bb1_eff[n] = bb1[n] + sum_h eY[h] * Wb1[513+h][n]
// (folds the constant eY contribution of inp@Wb1 into the bias)
// ---------------------------------------------------------------------------
__global__ void bb1eff_kernel(const float* __restrict__ Wb1,
                              const float* __restrict__ bb1) {
    int n = blockIdx.x * 256 + threadIdx.x;   // 8 blocks x 256 = 2048
    float acc = bb1[n];
    const float* w = Wb1 + (size_t)(1 + EX_DIM) * HB + n;
#pragma unroll 8
    for (int h = 0; h < HRNN; h++) acc += g_eY[h] * w[(size_t)h * HB];
    g_bb1eff[n] = acc;
}

// ---------------------------------------------------------------------------
// H1[r][c] = tanh( Xrow(r) @ Wx1[:,c] + bx1[c] )
// Xrow(r): r = j*256 + m;  j==0 -> Xbase[m];  j>=1 -> Xbase[m] + stoich[:, j-1]
// Each CTA: 8 rows x 1024 cols, 256 threads.
// ---------------------------------------------------------------------------
__global__ void h1_kernel(const float* __restrict__ X,
                          const float* __restrict__ stoich,
                          const float* __restrict__ Wx1,
                          const float* __restrict__ bx1,
                          const int* kpp, const int* qpp) {
    __shared__ float xs[8][DX];
    int tid = threadIdx.x;
    int r0 = blockIdx.x * 8;
    int kp = read_int(kpp), qp = read_int(qpp);
    int base = kp * MBAR;
    if (tid < 8 * DX) {
        int rowl = tid >> 4, d = tid & 15;
        int r = r0 + rowl;
        int j = r >> 8, m = r & 255;
        float v = X[((size_t)qp * TOTAL + base + m) * DX + d];
        if (j > 0) v += stoich[d * MR + (j - 1)];
        xs[rowl][d] = v;
    }
    __syncthreads();
#pragma unroll
    for (int ci = 0; ci < 4; ci++) {
        int col = ci * 256 + tid;
        float w[DX];
#pragma unroll
        for (int d = 0; d < DX; d++) w[d] = Wx1[d * HX + col];
        float b = bx1[col];
#pragma unroll
        for (int rowl = 0; rowl < 8; rowl++) {
            float acc = b;
#pragma unroll
            for (int d = 0; d < DX; d++) acc = fmaf(xs[rowl][d], w[d], acc);
            g_H1[(size_t)(r0 + rowl) * HX + col] = tanhf(acc);
        }
    }
}

// ---------------------------------------------------------------------------
// Tiled fp32 GEMM (128x64 CTA tile, BK=16, 8x4 register micro-tile).
// STAGE 2: g_EX  = g_H1 @ Wx2            + bx2                      (K=1024,N=512)
// STAGE 3: g_H2  = tanh(g_EX @ Wb1[1:513] + bb1eff + t(row)*Wb1[0]) (K=512, N=2048)
// STAGE 4: g_OUT = g_H2 @ Wb2            + bb2                      (K=2048,N=64)
// ---------------------------------------------------------------------------
template <int STAGE>
__global__ void __launch_bounds__(256) gemm_kernel(
    const float* __restrict__ B, const float* __restrict__ bias,
    const float* __restrict__ trow, const float* __restrict__ times_t,
    const float* __restrict__ times_tau, const int* __restrict__ kptr)
{
    constexpr int  N     = (STAGE == 2) ? EX_DIM : (STAGE == 3) ? HB : GOUT;
    constexpr int  K     = (STAGE == 2) ? HX     : (STAGE == 3) ? EX_DIM : HB;
    constexpr bool TANH  = (STAGE == 3);
    constexpr bool TTERM = (STAGE == 3);
    const float* A = (STAGE == 2) ? g_H1 : (STAGE == 3) ? g_EX : g_H2;
    float*       C = (STAGE == 2) ? g_EX : (STAGE == 3) ? g_H2 : g_OUT;
    const float* bptr = (STAGE == 3) ? (const float*)g_bb1eff : bias;

    __shared__ float As[BK][BM + 4];
    __shared__ float Bs[BK][BN];

    const int tid = threadIdx.x;
    const int tx = tid & 15, ty = tid >> 4;
    const float* Ablk = A + (size_t)blockIdx.y * BM * K;
    const float* Bblk = B + blockIdx.x * BN;

    float acc[8][4];
#pragma unroll
    for (int i = 0; i < 8; i++)
#pragma unroll
        for (int j = 0; j < 4; j++) acc[i][j] = 0.f;

    const int arow = tid >> 2;           // 0..63
    const int akq  = (tid & 3) * 4;      // 0,4,8,12
    const int brow = tid >> 4;           // 0..15
    const int bcol = (tid & 15) * 4;     // 0..60

    float4 a0 = *(const float4*)(Ablk + (size_t)arow * K + akq);
    float4 a1 = *(const float4*)(Ablk + (size_t)(arow + 64) * K + akq);
    float4 b0 = *(const float4*)(Bblk + (size_t)brow * N + bcol);

    constexpr int NTILES = K / BK;
    for (int kt = 0; kt < NTILES; kt++) {
        As[akq + 0][arow] = a0.x; As[akq + 1][arow] = a0.y;
        As[akq + 2][arow] = a0.z; As[akq + 3][arow] = a0.w;
        As[akq + 0][arow + 64] = a1.x; As[akq + 1][arow + 64] = a1.y;
        As[akq + 2][arow + 64] = a1.z; As[akq + 3][arow + 64] = a1.w;
        *(float4*)&Bs[brow][bcol] = b0;
        __syncthreads();
        if (kt + 1 < NTILES) {
            const float* An = Ablk + (kt + 1) * BK;
            a0 = *(const float4*)(An + (size_t)arow * K + akq);
            a1 = *(const float4*)(An + (size_t)(arow + 64) * K + akq);
            b0 = *(const float4*)(Bblk + (size_t)((kt + 1) * BK + brow) * N + bcol);
        }
#pragma unroll
        for (int kk = 0; kk < BK; kk++) {
            float4 av0 = *(const float4*)(&As[kk][ty * 8]);
            float4 av1 = *(const float4*)(&As[kk][ty * 8 + 4]);
            float4 bv  = *(const float4*)(&Bs[kk][tx * 4]);
            float a[8] = {av0.x, av0.y, av0.z, av0.w, av1.x, av1.y, av1.z, av1.w};
            float b[4] = {bv.x, bv.y, bv.z, bv.w};
#pragma unroll
            for (int i = 0; i < 8; i++)
#pragma unroll
                for (int j = 0; j < 4; j++)
                    acc[i][j] = fmaf(a[i], b[j], acc[i][j]);
        }
        __syncthreads();
    }

    // Epilogue
    const int row0 = blockIdx.y * BM + ty * 8;
    const int col0 = blockIdx.x * BN + tx * 4;
    float b4[4];
#pragma unroll
    for (int j = 0; j < 4; j++) b4[j] = bptr[col0 + j];
    float tr4[4] = {0.f, 0.f, 0.f, 0.f};
    float tbase = 0.f;
    if constexpr (TTERM) {
#pragma unroll
        for (int j = 0; j < 4; j++) tr4[j] = trow[col0 + j];
        tbase = times_t[read_int(kptr)];
    }
#pragma unroll
    for (int i = 0; i < 8; i++) {
        int row = row0 + i;
        float tv = 0.f;
        if constexpr (TTERM) tv = tbase + times_tau[row & 255];
        float v[4];
#pragma unroll
        for (int j = 0; j < 4; j++) {
            float x = acc[i][j] + b4[j];
            if constexpr (TTERM) x = fmaf(tv, tr4[j], x);
            if constexpr (TANH) x = tanhf(x);
            v[j] = x;
        }
        float4 o = {v[0], v[1], v[2], v[3]};
        *(float4*)(C + (size_t)row * N + col0) = o;
    }
}

// ---------------------------------------------------------------------------
// Reduction: partial[jj][g] = sum_m (OUT[(jj+1)*256+m][g] - OUT[m][g]) * w(m,jj)
// where w = valid(jj,m) * (R[q', base+1+m, jj] - R[q', base+m, jj])
// ---------------------------------------------------------------------------
__global__ void reduce_partial(const float* __restrict__ X,
                               const float* __restrict__ R,
                               const float* __restrict__ stoich,
                               const int* kpp, const int* qpp) {
    __shared__ float w_sh[MBAR];
    __shared__ float red[256];
    int jj = blockIdx.x, t = threadIdx.x;
    int kp = read_int(kpp), qp = read_int(qpp);
    int base = kp * MBAR;
    {
        int m = t;
        const float* xb = X + ((size_t)qp * TOTAL + base + m) * DX;
        bool valid = true;
#pragma unroll
        for (int d = 0; d < DX; d++)
            valid = valid && (xb[d] + stoich[d * MR + jj] >= 0.f);
        size_t rbase = ((size_t)qp * TOTAL + base + m) * MR + jj;
        float rd = R[rbase + MR] - R[rbase];
        w_sh[m] = valid ? rd : 0.f;
    }
    __syncthreads();
    int g = t & 63, c = t >> 6;  // 4 chunks of 64 m-values each
    float acc = 0.f;
    for (int mm = c * 64; mm < c * 64 + 64; mm++) {
        float w = w_sh[mm];
        acc += (g_OUT[(size_t)((jj + 1) * MBAR + mm) * GOUT + g]
              - g_OUT[(size_t)mm * GOUT + g]) * w;
    }
    red[t] = acc;
    __syncthreads();
    if (t < 64)
        g_partial[jj * GOUT + t] = red[t] + red[t + 64] + red[t + 128] + red[t + 192];
}

__global__ void final_kernel(float* __restrict__ out) {
    int g = threadIdx.x;  // 64 threads
    float acc = 0.f;
#pragma unroll 8
    for (int jj = 0; jj < MR; jj++) acc += g_partial[jj * GOUT + g];
    out[g] = acc;
}

// ---------------------------------------------------------------------------
// Launch
// ---------------------------------------------------------------------------
extern "C" void kernel_launch(void* const* d_in, const int* in_sizes, int n_in,
                              void* d_out, int out_size) {
    const float* X         = (const float*)d_in[0];
    const float* Y         = (const float*)d_in[1];
    const float* R         = (const float*)d_in[2];
    const float* stoich    = (const float*)d_in[3];
    const float* times_t   = (const float*)d_in[4];
    const float* times_tau = (const float*)d_in[5];
    const float* Wx1       = (const float*)d_in[6];
    const float* bx1       = (const float*)d_in[7];
    const float* Wx2       = (const float*)d_in[8];
    const float* bx2       = (const float*)d_in[9];
    const float* Wih       = (const float*)d_in[10];
    const float* Whh       = (const float*)d_in[11];
    const float* bh        = (const float*)d_in[12];
    const float* Wb1       = (const float*)d_in[13];
    const float* bb1       = (const float*)d_in[14];
    const float* Wb2       = (const float*)d_in[15];
    const float* bb2       = (const float*)d_in[16];
    const int*   kptr      = (const int*)d_in[17];
    const int*   kpptr     = (const int*)d_in[18];
    const int*   qptr      = (const int*)d_in[19];
    const int*   qpptr     = (const int*)d_in[20];
    float* out = (float*)d_out;

    rnn_kernel<<<1, HRNN>>>(Y, Wih, Whh, bh, kptr, qptr);
    bb1eff_kernel<<<HB / 256, 256>>>(Wb1, bb1);
    h1_kernel<<<M_TOTAL / 8, 256>>>(X, stoich, Wx1, bx1, kpptr, qpptr);

    // Stage 2: EX = H1 @ Wx2 + bx2
    gemm_kernel<2><<<dim3(EX_DIM / BN, M_TOTAL / BM), 256>>>(
        Wx2, bx2, nullptr, nullptr, nullptr, nullptr);
    // Stage 3: H2 = tanh(EX @ Wb1[1:513] + bb1eff + t*Wb1[0])
    gemm_kernel<3><<<dim3(HB / BN, M_TOTAL / BM), 256>>>(
        Wb1 + HB, nullptr, Wb1, times_t, times_tau, kptr);
    // Stage 4: OUT = H2 @ Wb2 + bb2
    gemm_kernel<4><<<dim3(GOUT / BN, M_TOTAL / BM), 256>>>(
        Wb2, bb2, nullptr, nullptr, nullptr, nullptr);

    reduce_partial<<<MR, 256>>>(X, R, stoich, kpptr, qpptr);
    final_kernel<<<1, GOUT>>>(out);
}

// round 4
// speedup vs baseline: 1.9766x; 1.9766x over previous
#include <cuda_runtime.h>
#include <cuda_bf16.h>
#include <cstdint>

// ---------------------------------------------------------------------------
// Problem constants
// ---------------------------------------------------------------------------
#define DX      16
#define DY      8
#define MR      64
#define MBAR    256
#define NT      9
#define GOUT    64
#define HX      1024
#define EX_DIM  512
#define HRNN    512
#define HB      2048
#define TOTAL   2049
#define M_TOTAL 16640           // (MR+1)*MBAR

// ---------------------------------------------------------------------------
// Scratch (__device__ globals; no allocations allowed).
// NOTE: these symbols must ONLY be referenced from device code (host code sees
// shadow objects whose address is NOT a device pointer).
// ---------------------------------------------------------------------------
__device__ __nv_bfloat16 g_H1h[(size_t)M_TOTAL * HX];
__device__ __nv_bfloat16 g_H1l[(size_t)M_TOTAL * HX];
__device__ __nv_bfloat16 g_EXh[(size_t)M_TOTAL * EX_DIM];
__device__ __nv_bfloat16 g_EXl[(size_t)M_TOTAL * EX_DIM];
__device__ __nv_bfloat16 g_H2h[(size_t)M_TOTAL * HB];
__device__ __nv_bfloat16 g_H2l[(size_t)M_TOTAL * HB];
__device__ __nv_bfloat16 g_W2Th[EX_DIM * HX],  g_W2Tl[EX_DIM * HX];   // [n][k]
__device__ __nv_bfloat16 g_W3Th[HB * EX_DIM],  g_W3Tl[HB * EX_DIM];   // [n][k]
__device__ __nv_bfloat16 g_W4Th[GOUT * HB],    g_W4Tl[GOUT * HB];     // [n][k]
__device__ float g_OUT[(size_t)M_TOTAL * GOUT];
__device__ float g_h0[HRNN], g_h1buf[HRNN];
__device__ float g_bb1eff[HB];
__device__ float g_partial[MR * GOUT];

__device__ __forceinline__ int read_int(const int* p) {
    int v = *p;
    if (v >= 0 && v < (1 << 20)) return v;
    return (int)__int_as_float(v);
}

// ---------------------------------------------------------------------------
// PTX helpers (base sm_103 target: cp.async + ldmatrix + mma.sync only)
// ---------------------------------------------------------------------------
__device__ __forceinline__ uint32_t smem_u32(const void* p) {
    uint32_t a;
    asm("{ .reg .u64 t; cvta.to.shared.u64 t, %1; cvt.u32.u64 %0, t; }"
        : "=r"(a) : "l"(p));
    return a;
}
__device__ __forceinline__ void cp16(uint32_t dst, const void* src) {
    asm volatile("cp.async.cg.shared.global [%0], [%1], 16;"
                 :: "r"(dst), "l"(src) : "memory");
}
#define CP_COMMIT() asm volatile("cp.async.commit_group;" ::: "memory")
#define CP_WAIT(n)  asm volatile("cp.async.wait_group %0;" :: "n"(n) : "memory")

#define LDSM4(r0, r1, r2, r3, addr)                                            \
    asm volatile("ldmatrix.sync.aligned.m8n8.x4.shared.b16 {%0,%1,%2,%3}, [%4];" \
                 : "=r"(r0), "=r"(r1), "=r"(r2), "=r"(r3) : "r"(addr))

#define MMA16816(d, a, b)                                                      \
    asm volatile("mma.sync.aligned.m16n8k16.row.col.f32.bf16.bf16.f32 "        \
                 "{%0,%1,%2,%3}, {%4,%5,%6,%7}, {%8,%9}, {%0,%1,%2,%3};"       \
                 : "+f"((d)[0]), "+f"((d)[1]), "+f"((d)[2]), "+f"((d)[3])      \
                 : "r"((a)[0]), "r"((a)[1]), "r"((a)[2]), "r"((a)[3]),         \
                   "r"((b)[0]), "r"((b)[1]))

// ---------------------------------------------------------------------------
// Weight prep: W<which>T[n*Kdim + k] = bf16 hi/lo split of
//              src[(rowOff + k)*srcStride + n]
// Destination arrays selected in DEVICE code via `which`.
// ---------------------------------------------------------------------------
__global__ void prep_w(const float* __restrict__ src, int srcStride, int rowOff,
                       int which, int Kdim) {
    __nv_bfloat16* dh;
    __nv_bfloat16* dl;
    if (which == 2)      { dh = g_W2Th; dl = g_W2Tl; }
    else if (which == 3) { dh = g_W3Th; dl = g_W3Tl; }
    else                 { dh = g_W4Th; dl = g_W4Tl; }

    __shared__ float t[32][33];
    int kb = blockIdx.x * 32, nb = blockIdx.y * 32;
    int tx = threadIdx.x, ty = threadIdx.y;
#pragma unroll
    for (int dy = 0; dy < 32; dy += 8)
        t[ty + dy][tx] = src[(size_t)(rowOff + kb + ty + dy) * srcStride + nb + tx];
    __syncthreads();
#pragma unroll
    for (int dy = 0; dy < 32; dy += 8) {
        int n = nb + ty + dy, k = kb + tx;
        float v = t[tx][ty + dy];
        __nv_bfloat16 h = __float2bfloat16(v);
        dh[(size_t)n * Kdim + k] = h;
        dl[(size_t)n * Kdim + k] = __float2bfloat16(v - __bfloat162float(h));
    }
}

// ---------------------------------------------------------------------------
// RNN: one step per launch, 8 CTAs x 64 threads. Buffers chosen device-side.
// ---------------------------------------------------------------------------
__global__ void rnn_init() { g_h0[blockIdx.x * 64 + threadIdx.x] = 0.f; }

__global__ void rnn_step(const float* __restrict__ Y, const float* __restrict__ Wih,
                         const float* __restrict__ Whh, const float* __restrict__ bh,
                         const int* kptr, const int* qptr, int s) {
    const float* hin  = (s & 1) ? g_h1buf : g_h0;
    float*       hout = (s & 1) ? g_h0    : g_h1buf;
    int i = blockIdx.x * 64 + threadIdx.x;
    int k = read_int(kptr), q = read_int(qptr);
    int steps = NT - 1 - k;
    if (s >= steps) { hout[i] = hin[i]; return; }
    const float* y = Y + ((size_t)q * NT + (k + 1 + s)) * DY;
    float acc = bh[i];
#pragma unroll
    for (int d = 0; d < DY; d++) acc += y[d] * Wih[d * HRNN + i];
    const float4* h4 = (const float4*)hin;
#pragma unroll 8
    for (int kk = 0; kk < HRNN / 4; kk++) {
        float4 hv = h4[kk];
        acc = fmaf(hv.x, Whh[(4 * kk + 0) * HRNN + i], acc);
        acc = fmaf(hv.y, Whh[(4 * kk + 1) * HRNN + i], acc);
        acc = fmaf(hv.z, Whh[(4 * kk + 2) * HRNN + i], acc);
        acc = fmaf(hv.w, Whh[(4 * kk + 3) * HRNN + i], acc);
    }
    hout[i] = tanhf(acc);
}

// bb1_eff[n] = bb1[n] + sum_h eY[h] * Wb1[513+h][n]   (eY lives in g_h0)
__global__ void bb1eff_kernel(const float* __restrict__ Wb1,
                              const float* __restrict__ bb1) {
    int n = blockIdx.x * 256 + threadIdx.x;
    float acc = bb1[n];
    const float* w = Wb1 + (size_t)(1 + EX_DIM) * HB + n;
#pragma unroll 8
    for (int h = 0; h < HRNN; h++) acc += g_h0[h] * w[(size_t)h * HB];
    g_bb1eff[n] = acc;
}

// ---------------------------------------------------------------------------
// H1 = tanh(Xrow @ Wx1 + bx1), split to bf16 hi/lo
// ---------------------------------------------------------------------------
__global__ void h1_kernel(const float* __restrict__ X,
                          const float* __restrict__ stoich,
                          const float* __restrict__ Wx1,
                          const float* __restrict__ bx1,
                          const int* kpp, const int* qpp) {
    __shared__ float xs[8][DX];
    int tid = threadIdx.x;
    int r0 = blockIdx.x * 8;
    int kp = read_int(kpp), qp = read_int(qpp);
    int base = kp * MBAR;
    if (tid < 8 * DX) {
        int rowl = tid >> 4, d = tid & 15;
        int r = r0 + rowl;
        int j = r >> 8, m = r & 255;
        float v = X[((size_t)qp * TOTAL + base + m) * DX + d];
        if (j > 0) v += stoich[d * MR + (j - 1)];
        xs[rowl][d] = v;
    }
    __syncthreads();
#pragma unroll
    for (int ci = 0; ci < 4; ci++) {
        int col = ci * 256 + tid;
        float w[DX];
#pragma unroll
        for (int d = 0; d < DX; d++) w[d] = Wx1[d * HX + col];
        float b = bx1[col];
#pragma unroll
        for (int rowl = 0; rowl < 8; rowl++) {
            float acc = b;
#pragma unroll
            for (int d = 0; d < DX; d++) acc = fmaf(xs[rowl][d], w[d], acc);
            float v = tanhf(acc);
            __nv_bfloat16 h = __float2bfloat16(v);
            size_t idx = (size_t)(r0 + rowl) * HX + col;
            g_H1h[idx] = h;
            g_H1l[idx] = __float2bfloat16(v - __bfloat162float(h));
        }
    }
}

// ---------------------------------------------------------------------------
// HMMA GEMM: C[M_TOTAL, NTOT] = A[M_TOTAL, KDIM] @ B[NTOT, KDIM]^T
// 3-pass bf16 hi/lo split (Ah*Bh + Al*Bh + Ah*Bl), fp32 accum in registers.
// CTA 128 x BN, BK=32, 8 warps (2x4), warp tile 64 x BN/4.
// 2-stage cp.async pipeline; XOR swizzle conflict-free for cp.async+ldmatrix.
// MODE 2: EX  = H1@W2T + bx2                        -> split bf16
// MODE 3: H2  = tanh(EX@W3T + bb1eff + t*Wb1row0)   -> split bf16
// MODE 4: OUT = H2@W4T + bb2                        -> fp32
// ---------------------------------------------------------------------------
template <int MODE, int KDIM, int NTOT, int BN>
__global__ void __launch_bounds__(256, 1) mma_gemm(
    const float* __restrict__ bias, const float* __restrict__ trow,
    const float* __restrict__ times_t, const float* __restrict__ times_tau,
    const int* __restrict__ kptr)
{
    constexpr int NCH = KDIM / 32;
    constexpr int WN  = BN / 4;     // warp n width (32 or 16)
    constexpr int NB  = WN / 8;     // n8 tiles per warp (4 or 2)
    constexpr int NBL = WN / 16;    // x4 B loads per kstep (2 or 1)
    constexpr int AT  = 128 * 64;   // bytes per A material (128 rows x 64B)
    constexpr int BT  = BN * 64;
    constexpr int STAGE = 2 * AT + 2 * BT;

    const __nv_bfloat16* Aph = (MODE == 2) ? g_H1h : (MODE == 3) ? g_EXh : g_H2h;
    const __nv_bfloat16* Apl = (MODE == 2) ? g_H1l : (MODE == 3) ? g_EXl : g_H2l;
    const __nv_bfloat16* Bph = (MODE == 2) ? g_W2Th : (MODE == 3) ? g_W3Th : g_W4Th;
    const __nv_bfloat16* Bpl = (MODE == 2) ? g_W2Tl : (MODE == 3) ? g_W3Tl : g_W4Tl;
    const float* bptr = (MODE == 3) ? (const float*)g_bb1eff : bias;

    extern __shared__ char dsm[];
    char* basep = (char*)(((uintptr_t)dsm + 127) & ~(uintptr_t)127);
    const uint32_t baseu = smem_u32(basep);

    const int tid  = threadIdx.x;
    const int lane = tid & 31, wid = tid >> 5;
    const int warp_m = wid >> 2, warp_n = wid & 3;
    const size_t growBase = (size_t)blockIdx.y * 128;
    const int nbase = blockIdx.x * BN;

    float acc[4][NB][4];
#pragma unroll
    for (int i = 0; i < 4; i++)
#pragma unroll
        for (int j = 0; j < NB; j++)
#pragma unroll
            for (int v = 0; v < 4; v++) acc[i][j][v] = 0.f;

    // ldmatrix smem offsets (relative to stage base; ^32 selects second kstep)
    uint32_t aoff[4];
    {
        int r16 = lane & 15, half = lane >> 4;
#pragma unroll
        for (int i = 0; i < 4; i++) {
            int row = warp_m * 64 + i * 16 + r16;
            int perm = half ^ (row & 3) ^ ((row >> 2) & 1);
            aoff[i] = row * 64 + (perm << 4);
        }
    }
    uint32_t boff[NBL];
    {
        int rn = (lane >> 4) * 8 + (lane & 7);
        int c  = (lane >> 3) & 1;
#pragma unroll
        for (int j = 0; j < NBL; j++) {
            int row = warp_n * WN + j * 16 + rn;
            int perm = c ^ (row & 3) ^ ((row >> 2) & 1);
            boff[j] = 2 * AT + row * 64 + (perm << 4);
        }
    }

    auto load_chunk = [&](int cc) {
        uint32_t tb = baseu + (uint32_t)(cc & 1) * STAGE;
        int k0 = cc * 32;
#pragma unroll
        for (int it = 0; it < 2; it++) {           // A: 512 chunks / 256 threads
            int idx = it * 256 + tid;
            int r = idx >> 2, c = idx & 3;
            uint32_t perm = (uint32_t)(c ^ (r & 3) ^ ((r >> 2) & 1));
            uint32_t d = tb + r * 64 + (perm << 4);
            const __nv_bfloat16* sh = Aph + (growBase + r) * KDIM + k0 + c * 8;
            const __nv_bfloat16* sl = Apl + (growBase + r) * KDIM + k0 + c * 8;
            cp16(d, sh);
            cp16(d + AT, sl);
        }
#pragma unroll
        for (int it = 0; it < BN / 64; it++) {     // B: BN*4 chunks
            int idx = it * 256 + tid;
            int r = idx >> 2, c = idx & 3;
            uint32_t perm = (uint32_t)(c ^ (r & 3) ^ ((r >> 2) & 1));
            uint32_t d = tb + 2 * AT + r * 64 + (perm << 4);
            const __nv_bfloat16* sh = Bph + (size_t)(nbase + r) * KDIM + k0 + c * 8;
            const __nv_bfloat16* sl = Bpl + (size_t)(nbase + r) * KDIM + k0 + c * 8;
            cp16(d, sh);
            cp16(d + BT, sl);
        }
        CP_COMMIT();
    };

    load_chunk(0);

    for (int ch = 0; ch < NCH; ch++) {
        if (ch + 1 < NCH) {
            load_chunk(ch + 1);
            CP_WAIT(1);
        } else {
            CP_WAIT(0);
        }
        __syncthreads();
        uint32_t tb = baseu + (uint32_t)(ch & 1) * STAGE;
#pragma unroll
        for (int kk = 0; kk < 2; kk++) {
            uint32_t kx = kk ? 32u : 0u;
            uint32_t fah[4][4], fal[4][4], fbh[NB][2], fbl[NB][2];
#pragma unroll
            for (int i = 0; i < 4; i++) {
                uint32_t a = tb + (aoff[i] ^ kx);
                LDSM4(fah[i][0], fah[i][1], fah[i][2], fah[i][3], a);
                LDSM4(fal[i][0], fal[i][1], fal[i][2], fal[i][3], a + AT);
            }
#pragma unroll
            for (int j = 0; j < NBL; j++) {
                uint32_t b = tb + (boff[j] ^ kx);
                LDSM4(fbh[2 * j][0], fbh[2 * j][1], fbh[2 * j + 1][0], fbh[2 * j + 1][1], b);
                LDSM4(fbl[2 * j][0], fbl[2 * j][1], fbl[2 * j + 1][0], fbl[2 * j + 1][1], b + BT);
            }
#pragma unroll
            for (int mi = 0; mi < 4; mi++)
#pragma unroll
                for (int nj = 0; nj < NB; nj++) {
                    MMA16816(acc[mi][nj], fah[mi], fbh[nj]);
                    MMA16816(acc[mi][nj], fal[mi], fbh[nj]);
                    MMA16816(acc[mi][nj], fah[mi], fbl[nj]);
                }
        }
        __syncthreads();
    }

    // ---------------- Epilogue ----------------
    const int r_in = lane >> 2, c2 = (lane & 3) * 2;
    float tbase = 0.f;
    if (MODE == 3) tbase = times_t[read_int(kptr)];

#pragma unroll
    for (int mi = 0; mi < 4; mi++) {
        size_t rowA = growBase + warp_m * 64 + mi * 16 + r_in;
        size_t rowB = rowA + 8;
        float tA = 0.f, tB = 0.f;
        if (MODE == 3) {
            tA = tbase + times_tau[rowA & 255];
            tB = tbase + times_tau[rowB & 255];
        }
#pragma unroll
        for (int nj = 0; nj < NB; nj++) {
            int col = nbase + warp_n * WN + nj * 8 + c2;
            float b0 = bptr[col], b1 = bptr[col + 1];
            float v00 = acc[mi][nj][0] + b0;
            float v01 = acc[mi][nj][1] + b1;
            float v10 = acc[mi][nj][2] + b0;
            float v11 = acc[mi][nj][3] + b1;
            if (MODE == 3) {
                float tr0 = trow[col], tr1 = trow[col + 1];
                v00 = tanhf(fmaf(tA, tr0, v00));
                v01 = tanhf(fmaf(tA, tr1, v01));
                v10 = tanhf(fmaf(tB, tr0, v10));
                v11 = tanhf(fmaf(tB, tr1, v11));
            }
            if (MODE == 4) {
                float2 oA = {v00, v01}, oB = {v10, v11};
                *(float2*)(g_OUT + rowA * GOUT + col) = oA;
                *(float2*)(g_OUT + rowB * GOUT + col) = oB;
            } else {
                __nv_bfloat16* Ch = (MODE == 2) ? g_EXh : g_H2h;
                __nv_bfloat16* Cl = (MODE == 2) ? g_EXl : g_H2l;
                __nv_bfloat16 h00 = __float2bfloat16(v00);
                __nv_bfloat16 h01 = __float2bfloat16(v01);
                __nv_bfloat16 h10 = __float2bfloat16(v10);
                __nv_bfloat16 h11 = __float2bfloat16(v11);
                *(__nv_bfloat162*)(Ch + rowA * NTOT + col) = __halves2bfloat162(h00, h01);
                *(__nv_bfloat162*)(Ch + rowB * NTOT + col) = __halves2bfloat162(h10, h11);
                *(__nv_bfloat162*)(Cl + rowA * NTOT + col) = __halves2bfloat162(
                    __float2bfloat16(v00 - __bfloat162float(h00)),
                    __float2bfloat16(v01 - __bfloat162float(h01)));
                *(__nv_bfloat162*)(Cl + rowB * NTOT + col) = __halves2bfloat162(
                    __float2bfloat16(v10 - __bfloat162float(h10)),
                    __float2bfloat16(v11 - __bfloat162float(h11)));
            }
        }
    }
}

// ---------------------------------------------------------------------------
// Reduction
// ---------------------------------------------------------------------------
__global__ void reduce_partial(const float* __restrict__ X,
                               const float* __restrict__ R,
                               const float* __restrict__ stoich,
                               const int* kpp, const int* qpp) {
    __shared__ float w_sh[MBAR];
    __shared__ float red[256];
    int jj = blockIdx.x, t = threadIdx.x;
    int kp = read_int(kpp), qp = read_int(qpp);
    int base = kp * MBAR;
    {
        int m = t;
        const float* xb = X + ((size_t)qp * TOTAL + base + m) * DX;
        bool valid = true;
#pragma unroll
        for (int d = 0; d < DX; d++)
            valid = valid && (xb[d] + stoich[d * MR + jj] >= 0.f);
        size_t rbase = ((size_t)qp * TOTAL + base + m) * MR + jj;
        float rd = R[rbase + MR] - R[rbase];
        w_sh[m] = valid ? rd : 0.f;
    }
    __syncthreads();
    int g = t & 63, c = t >> 6;
    float acc = 0.f;
    for (int mm = c * 64; mm < c * 64 + 64; mm++) {
        float w = w_sh[mm];
        acc += (g_OUT[(size_t)((jj + 1) * MBAR + mm) * GOUT + g]
              - g_OUT[(size_t)mm * GOUT + g]) * w;
    }
    red[t] = acc;
    __syncthreads();
    if (t < 64)
        g_partial[jj * GOUT + t] = red[t] + red[t + 64] + red[t + 128] + red[t + 192];
}

__global__ void final_kernel(float* __restrict__ out) {
    int g = threadIdx.x;
    float acc = 0.f;
#pragma unroll 8
    for (int jj = 0; jj < MR; jj++) acc += g_partial[jj * GOUT + g];
    out[g] = acc;
}

// ---------------------------------------------------------------------------
// Launch
// ---------------------------------------------------------------------------
extern "C" void kernel_launch(void* const* d_in, const int* in_sizes, int n_in,
                              void* d_out, int out_size) {
    const float* X         = (const float*)d_in[0];
    const float* Y         = (const float*)d_in[1];
    const float* R         = (const float*)d_in[2];
    const float* stoich    = (const float*)d_in[3];
    const float* times_t   = (const float*)d_in[4];
    const float* times_tau = (const float*)d_in[5];
    const float* Wx1       = (const float*)d_in[6];
    const float* bx1       = (const float*)d_in[7];
    const float* Wx2       = (const float*)d_in[8];
    const float* bx2       = (const float*)d_in[9];
    const float* Wih       = (const float*)d_in[10];
    const float* Whh       = (const float*)d_in[11];
    const float* bh        = (const float*)d_in[12];
    const float* Wb1       = (const float*)d_in[13];
    const float* bb1       = (const float*)d_in[14];
    const float* Wb2       = (const float*)d_in[15];
    const float* bb2       = (const float*)d_in[16];
    const int*   kptr      = (const int*)d_in[17];
    const int*   kpptr     = (const int*)d_in[18];
    const int*   qptr      = (const int*)d_in[19];
    const int*   qpptr     = (const int*)d_in[20];
    float* out = (float*)d_out;

    constexpr int SM23 = 2 * (2 * 128 * 64 + 2 * 128 * 64) + 256;  // 65792
    constexpr int SM4  = 2 * (2 * 128 * 64 + 2 * 64 * 64) + 256;   // 49408
    cudaFuncSetAttribute(mma_gemm<2, HX, EX_DIM, 128>,
                         cudaFuncAttributeMaxDynamicSharedMemorySize, SM23);
    cudaFuncSetAttribute(mma_gemm<3, EX_DIM, HB, 128>,
                         cudaFuncAttributeMaxDynamicSharedMemorySize, SM23);
    cudaFuncSetAttribute(mma_gemm<4, HB, GOUT, 64>,
                         cudaFuncAttributeMaxDynamicSharedMemorySize, SM4);

    // Weight transpose + hi/lo split (dst arrays selected device-side)
    prep_w<<<dim3(HX / 32, EX_DIM / 32), dim3(32, 8)>>>(Wx2, EX_DIM, 0, 2, HX);
    prep_w<<<dim3(EX_DIM / 32, HB / 32), dim3(32, 8)>>>(Wb1, HB, 1, 3, EX_DIM);
    prep_w<<<dim3(HB / 32, GOUT / 32), dim3(32, 8)>>>(Wb2, GOUT, 0, 4, HB);

    // RNN: 8 fixed step launches; buffers chosen device-side; result in g_h0
    rnn_init<<<8, 64>>>();
    for (int s = 0; s < NT - 1; s++)
        rnn_step<<<8, 64>>>(Y, Wih, Whh, bh, kptr, qptr, s);
    bb1eff_kernel<<<HB / 256, 256>>>(Wb1, bb1);

    h1_kernel<<<M_TOTAL / 8, 256>>>(X, stoich, Wx1, bx1, kpptr, qpptr);

    mma_gemm<2, HX, EX_DIM, 128><<<dim3(EX_DIM / 128, M_TOTAL / 128), 256, SM23>>>(
        bx2, nullptr, nullptr, nullptr, nullptr);
    mma_gemm<3, EX_DIM, HB, 128><<<dim3(HB / 128, M_TOTAL / 128), 256, SM23>>>(
        nullptr, Wb1, times_t, times_tau, kptr);
    mma_gemm<4, HB, GOUT, 64><<<dim3(1, M_TOTAL / 128), 256, SM4>>>(
        bb2, nullptr, nullptr, nullptr, nullptr);

    reduce_partial<<<MR, 256>>>(X, R, stoich, kpptr, qpptr);
    final_kernel<<<1, GOUT>>>(out);
}

// round 5
// speedup vs baseline: 2.1609x; 1.0932x over previous
#include <cuda_runtime.h>
#include <cuda_bf16.h>
#include <cstdint>

// ---------------------------------------------------------------------------
// Problem constants
// ---------------------------------------------------------------------------
#define DX      16
#define DY      8
#define MR      64
#define MBAR    256
#define NT      9
#define GOUT    64
#define HX      1024
#define EX_DIM  512
#define HRNN    512
#define HB      2048
#define TOTAL   2049
#define M_TOTAL 16640           // (MR+1)*MBAR

// ---------------------------------------------------------------------------
// Scratch (__device__ globals; referenced ONLY from device code)
// ---------------------------------------------------------------------------
__device__ __nv_bfloat16 g_H1h[(size_t)M_TOTAL * HX];
__device__ __nv_bfloat16 g_H1l[(size_t)M_TOTAL * HX];
__device__ __nv_bfloat16 g_EXh[(size_t)M_TOTAL * EX_DIM];
__device__ __nv_bfloat16 g_EXl[(size_t)M_TOTAL * EX_DIM];
__device__ __nv_bfloat16 g_H2h[(size_t)M_TOTAL * HB];
__device__ __nv_bfloat16 g_H2l[(size_t)M_TOTAL * HB];
__device__ __nv_bfloat16 g_W2Th[EX_DIM * HX],  g_W2Tl[EX_DIM * HX];   // [n][k]
__device__ __nv_bfloat16 g_W3Th[HB * EX_DIM],  g_W3Tl[HB * EX_DIM];   // [n][k]
__device__ __nv_bfloat16 g_W4Th[GOUT * HB],    g_W4Tl[GOUT * HB];     // [n][k]
__device__ float g_OUT[(size_t)M_TOTAL * GOUT];
__device__ float g_h0[HRNN], g_h1buf[HRNN];
__device__ float g_bb1eff[HB];
__device__ float g_partial[MR * GOUT];
__device__ float g_basepre[MBAR * HX];   // base pre-activations (bx1 folded in)
__device__ float g_delta[MR * HX];       // per-reaction pre-activation deltas

__device__ __forceinline__ int read_int(const int* p) {
    int v = *p;
    if (v >= 0 && v < (1 << 20)) return v;
    return (int)__int_as_float(v);
}

// Fast tanh: 1 - 2/(e^{2x}+1). ~1e-6 abs err; 2 MUFU + few ALU.
__device__ __forceinline__ float fast_tanh(float x) {
    float e = __expf(2.f * x);
    return 1.f - __fdividef(2.f, e + 1.f);
}

// ---------------------------------------------------------------------------
// PTX helpers (base sm_103 target: cp.async + ldmatrix + mma.sync only)
// ---------------------------------------------------------------------------
__device__ __forceinline__ uint32_t smem_u32(const void* p) {
    uint32_t a;
    asm("{ .reg .u64 t; cvta.to.shared.u64 t, %1; cvt.u32.u64 %0, t; }"
        : "=r"(a) : "l"(p));
    return a;
}
__device__ __forceinline__ void cp16(uint32_t dst, const void* src) {
    asm volatile("cp.async.cg.shared.global [%0], [%1], 16;"
                 :: "r"(dst), "l"(src) : "memory");
}
#define CP_COMMIT() asm volatile("cp.async.commit_group;" ::: "memory")
#define CP_WAIT(n)  asm volatile("cp.async.wait_group %0;" :: "n"(n) : "memory")

#define LDSM4(r0, r1, r2, r3, addr)                                            \
    asm volatile("ldmatrix.sync.aligned.m8n8.x4.shared.b16 {%0,%1,%2,%3}, [%4];" \
                 : "=r"(r0), "=r"(r1), "=r"(r2), "=r"(r3) : "r"(addr))

#define MMA16816(d, a, b)                                                      \
    asm volatile("mma.sync.aligned.m16n8k16.row.col.f32.bf16.bf16.f32 "        \
                 "{%0,%1,%2,%3}, {%4,%5,%6,%7}, {%8,%9}, {%0,%1,%2,%3};"       \
                 : "+f"((d)[0]), "+f"((d)[1]), "+f"((d)[2]), "+f"((d)[3])      \
                 : "r"((a)[0]), "r"((a)[1]), "r"((a)[2]), "r"((a)[3]),         \
                   "r"((b)[0]), "r"((b)[1]))

// ---------------------------------------------------------------------------
// Weight prep: W<which>T[n*Kdim + k] = bf16 hi/lo split of
//              src[(rowOff + k)*srcStride + n]
// ---------------------------------------------------------------------------
__global__ void prep_w(const float* __restrict__ src, int srcStride, int rowOff,
                       int which, int Kdim) {
    __nv_bfloat16* dh;
    __nv_bfloat16* dl;
    if (which == 2)      { dh = g_W2Th; dl = g_W2Tl; }
    else if (which == 3) { dh = g_W3Th; dl = g_W3Tl; }
    else                 { dh = g_W4Th; dl = g_W4Tl; }

    __shared__ float t[32][33];
    int kb = blockIdx.x * 32, nb = blockIdx.y * 32;
    int tx = threadIdx.x, ty = threadIdx.y;
#pragma unroll
    for (int dy = 0; dy < 32; dy += 8)
        t[ty + dy][tx] = src[(size_t)(rowOff + kb + ty + dy) * srcStride + nb + tx];
    __syncthreads();
#pragma unroll
    for (int dy = 0; dy < 32; dy += 8) {
        int n = nb + ty + dy, k = kb + tx;
        float v = t[tx][ty + dy];
        __nv_bfloat16 h = __float2bfloat16(v);
        dh[(size_t)n * Kdim + k] = h;
        dl[(size_t)n * Kdim + k] = __float2bfloat16(v - __bfloat162float(h));
    }
}

// ---------------------------------------------------------------------------
// RNN: one step per launch, 8 CTAs x 64 threads. Buffers chosen device-side.
// ---------------------------------------------------------------------------
__global__ void rnn_init() { g_h0[blockIdx.x * 64 + threadIdx.x] = 0.f; }

__global__ void rnn_step(const float* __restrict__ Y, const float* __restrict__ Wih,
                         const float* __restrict__ Whh, const float* __restrict__ bh,
                         const int* kptr, const int* qptr, int s) {
    const float* hin  = (s & 1) ? g_h1buf : g_h0;
    float*       hout = (s & 1) ? g_h0    : g_h1buf;
    int i = blockIdx.x * 64 + threadIdx.x;
    int k = read_int(kptr), q = read_int(qptr);
    int steps = NT - 1 - k;
    if (s >= steps) { hout[i] = hin[i]; return; }
    const float* y = Y + ((size_t)q * NT + (k + 1 + s)) * DY;
    float acc = bh[i];
#pragma unroll
    for (int d = 0; d < DY; d++) acc += y[d] * Wih[d * HRNN + i];
    const float4* h4 = (const float4*)hin;
#pragma unroll 8
    for (int kk = 0; kk < HRNN / 4; kk++) {
        float4 hv = h4[kk];
        acc = fmaf(hv.x, Whh[(4 * kk + 0) * HRNN + i], acc);
        acc = fmaf(hv.y, Whh[(4 * kk + 1) * HRNN + i], acc);
        acc = fmaf(hv.z, Whh[(4 * kk + 2) * HRNN + i], acc);
        acc = fmaf(hv.w, Whh[(4 * kk + 3) * HRNN + i], acc);
    }
    hout[i] = tanhf(acc);
}

// bb1_eff[n] = bb1[n] + sum_h eY[h] * Wb1[513+h][n]   (eY lives in g_h0)
__global__ void bb1eff_kernel(const float* __restrict__ Wb1,
                              const float* __restrict__ bb1) {
    int n = blockIdx.x * 256 + threadIdx.x;
    float acc = bb1[n];
    const float* w = Wb1 + (size_t)(1 + EX_DIM) * HB + n;
#pragma unroll 8
    for (int h = 0; h < HRNN; h++) acc += g_h0[h] * w[(size_t)h * HB];
    g_bb1eff[n] = acc;
}

// ---------------------------------------------------------------------------
// Pre-activations: rows 0..255 -> base_pre[m] = Xbase[m]@Wx1 + bx1
//                  rows 256..319 -> delta[j]  = stoich[:,j]@Wx1
// ---------------------------------------------------------------------------
__global__ void pre_h1_kernel(const float* __restrict__ X,
                              const float* __restrict__ stoich,
                              const float* __restrict__ Wx1,
                              const float* __restrict__ bx1,
                              const int* kpp, const int* qpp) {
    __shared__ float xv[DX];
    int row = blockIdx.x;        // 0..319
    int tid = threadIdx.x;
    int kp = read_int(kpp), qp = read_int(qpp);
    int base = kp * MBAR;
    if (tid < DX) {
        xv[tid] = (row < MBAR)
            ? X[((size_t)qp * TOTAL + base + row) * DX + tid]
            : stoich[tid * MR + (row - MBAR)];
    }
    __syncthreads();
#pragma unroll
    for (int ci = 0; ci < 4; ci++) {
        int col = ci * 256 + tid;
        float acc = (row < MBAR) ? bx1[col] : 0.f;
#pragma unroll
        for (int d = 0; d < DX; d++) acc = fmaf(xv[d], Wx1[d * HX + col], acc);
        if (row < MBAR) g_basepre[row * HX + col] = acc;
        else            g_delta[(row - MBAR) * HX + col] = acc;
    }
}

// ---------------------------------------------------------------------------
// H1 = tanh(base_pre[m] + delta[j-1]), split to bf16 hi/lo
// ---------------------------------------------------------------------------
__global__ void h1_kernel() {
    int tid = threadIdx.x;
    int r0 = blockIdx.x * 8;
#pragma unroll
    for (int rowl = 0; rowl < 8; rowl++) {
        int r = r0 + rowl;
        int j = r >> 8, m = r & 255;
        const float* bp = g_basepre + (size_t)m * HX;
        const float* dp = (j > 0) ? (g_delta + (size_t)(j - 1) * HX) : nullptr;
#pragma unroll
        for (int ci = 0; ci < 4; ci++) {
            int col = ci * 256 + tid;
            float pre = bp[col];
            if (j > 0) pre += dp[col];
            float v = fast_tanh(pre);
            __nv_bfloat16 h = __float2bfloat16(v);
            size_t idx = (size_t)r * HX + col;
            g_H1h[idx] = h;
            g_H1l[idx] = __float2bfloat16(v - __bfloat162float(h));
        }
    }
}

// ---------------------------------------------------------------------------
// HMMA GEMM: C[M_TOTAL, NTOT] = A[M_TOTAL, KDIM] @ B[NTOT, KDIM]^T
// 3-pass bf16 hi/lo split, fp32 accum. CTA 128 x BN, BK=32, 8 warps (2 x 4),
// warp tile 64 x (BN/4). 3-stage cp.async pipeline; XOR-swizzled smem.
// MODE 2: EX  = H1@W2T + bx2                        -> split bf16
// MODE 3: H2  = tanh(EX@W3T + bb1eff + t*Wb1row0)   -> split bf16
// MODE 4: OUT = H2@W4T + bb2                        -> fp32
// ---------------------------------------------------------------------------
template <int MODE, int KDIM, int NTOT, int BN>
__global__ void __launch_bounds__(256, 1) mma_gemm(
    const float* __restrict__ bias, const float* __restrict__ trow,
    const float* __restrict__ times_t, const float* __restrict__ times_tau,
    const int* __restrict__ kptr)
{
    constexpr int NCH = KDIM / 32;
    constexpr int WN  = BN / 4;     // warp n width (64 or 16)
    constexpr int NB  = WN / 8;     // n8 tiles per warp
    constexpr int NBL = WN / 16;    // x4 B loads per kstep
    constexpr int AT  = 128 * 64;   // bytes per A material per stage
    constexpr int BT  = BN * 64;
    constexpr int STAGE = 2 * AT + 2 * BT;

    const __nv_bfloat16* Aph = (MODE == 2) ? g_H1h : (MODE == 3) ? g_EXh : g_H2h;
    const __nv_bfloat16* Apl = (MODE == 2) ? g_H1l : (MODE == 3) ? g_EXl : g_H2l;
    const __nv_bfloat16* Bph = (MODE == 2) ? g_W2Th : (MODE == 3) ? g_W3Th : g_W4Th;
    const __nv_bfloat16* Bpl = (MODE == 2) ? g_W2Tl : (MODE == 3) ? g_W3Tl : g_W4Tl;
    const float* bptr = (MODE == 3) ? (const float*)g_bb1eff : bias;

    extern __shared__ char dsm[];
    char* basep = (char*)(((uintptr_t)dsm + 127) & ~(uintptr_t)127);
    const uint32_t baseu = smem_u32(basep);

    const int tid  = threadIdx.x;
    const int lane = tid & 31, wid = tid >> 5;
    const int warp_m = wid >> 2, warp_n = wid & 3;
    const size_t growBase = (size_t)blockIdx.y * 128;
    const int nbase = blockIdx.x * BN;

    float acc[4][NB][4];
#pragma unroll
    for (int i = 0; i < 4; i++)
#pragma unroll
        for (int j = 0; j < NB; j++)
#pragma unroll
            for (int v = 0; v < 4; v++) acc[i][j][v] = 0.f;

    // ldmatrix smem offsets (relative to stage base; ^32 selects second kstep)
    uint32_t aoff[4];
    {
        int r16 = lane & 15, half = lane >> 4;
#pragma unroll
        for (int i = 0; i < 4; i++) {
            int row = warp_m * 64 + i * 16 + r16;
            int perm = half ^ (row & 3) ^ ((row >> 2) & 1);
            aoff[i] = row * 64 + (perm << 4);
        }
    }
    uint32_t boff[NBL];
    {
        int rn = (lane >> 4) * 8 + (lane & 7);
        int c  = (lane >> 3) & 1;
#pragma unroll
        for (int j = 0; j < NBL; j++) {
            int row = warp_n * WN + j * 16 + rn;
            int perm = c ^ (row & 3) ^ ((row >> 2) & 1);
            boff[j] = 2 * AT + row * 64 + (perm << 4);
        }
    }

    auto load_chunk = [&](int cc) {
        uint32_t tb = baseu + (uint32_t)(cc % 3) * STAGE;
        int k0 = cc * 32;
#pragma unroll
        for (int it = 0; it < 2; it++) {           // A: 512 16B slots
            int idx = it * 256 + tid;
            int r = idx >> 2, c = idx & 3;
            uint32_t perm = (uint32_t)(c ^ (r & 3) ^ ((r >> 2) & 1));
            uint32_t d = tb + r * 64 + (perm << 4);
            const __nv_bfloat16* sh = Aph + (growBase + r) * KDIM + k0 + c * 8;
            const __nv_bfloat16* sl = Apl + (growBase + r) * KDIM + k0 + c * 8;
            cp16(d, sh);
            cp16(d + AT, sl);
        }
#pragma unroll
        for (int it = 0; it < BN / 64; it++) {     // B: BN*4 16B slots
            int idx = it * 256 + tid;
            int r = idx >> 2, c = idx & 3;
            uint32_t perm = (uint32_t)(c ^ (r & 3) ^ ((r >> 2) & 1));
            uint32_t d = tb + 2 * AT + r * 64 + (perm << 4);
            const __nv_bfloat16* sh = Bph + (size_t)(nbase + r) * KDIM + k0 + c * 8;
            const __nv_bfloat16* sl = Bpl + (size_t)(nbase + r) * KDIM + k0 + c * 8;
            cp16(d, sh);
            cp16(d + BT, sl);
        }
        CP_COMMIT();
    };

    load_chunk(0);
    load_chunk(1);

    for (int ch = 0; ch < NCH; ch++) {
        if (ch + 2 < NCH) {
            load_chunk(ch + 2);
            CP_WAIT(2);
        } else if (ch + 1 < NCH) {
            CP_WAIT(1);
        } else {
            CP_WAIT(0);
        }
        __syncthreads();
        uint32_t tb = baseu + (uint32_t)(ch % 3) * STAGE;
#pragma unroll
        for (int kk = 0; kk < 2; kk++) {
            uint32_t kx = kk ? 32u : 0u;
            uint32_t fbh[NB][2], fbl[NB][2];
#pragma unroll
            for (int j = 0; j < NBL; j++) {
                uint32_t b = tb + (boff[j] ^ kx);
                LDSM4(fbh[2 * j][0], fbh[2 * j][1], fbh[2 * j + 1][0], fbh[2 * j + 1][1], b);
                LDSM4(fbl[2 * j][0], fbl[2 * j][1], fbl[2 * j + 1][0], fbl[2 * j + 1][1], b + BT);
            }
#pragma unroll
            for (int mi = 0; mi < 4; mi++) {
                uint32_t fah[4], fal[4];
                uint32_t a = tb + (aoff[mi] ^ kx);
                LDSM4(fah[0], fah[1], fah[2], fah[3], a);
                LDSM4(fal[0], fal[1], fal[2], fal[3], a + AT);
#pragma unroll
                for (int nj = 0; nj < NB; nj++) {
                    MMA16816(acc[mi][nj], fah, fbh[nj]);
                    MMA16816(acc[mi][nj], fal, fbh[nj]);
                    MMA16816(acc[mi][nj], fah, fbl[nj]);
                }
            }
        }
        __syncthreads();
    }

    // ---------------- Epilogue ----------------
    const int r_in = lane >> 2, c2 = (lane & 3) * 2;
    float tbase = 0.f;
    if (MODE == 3) tbase = times_t[read_int(kptr)];

#pragma unroll
    for (int mi = 0; mi < 4; mi++) {
        size_t rowA = growBase + warp_m * 64 + mi * 16 + r_in;
        size_t rowB = rowA + 8;
        float tA = 0.f, tB = 0.f;
        if (MODE == 3) {
            tA = tbase + times_tau[rowA & 255];
            tB = tbase + times_tau[rowB & 255];
        }
#pragma unroll
        for (int nj = 0; nj < NB; nj++) {
            int col = nbase + warp_n * WN + nj * 8 + c2;
            float b0 = bptr[col], b1 = bptr[col + 1];
            float v00 = acc[mi][nj][0] + b0;
            float v01 = acc[mi][nj][1] + b1;
            float v10 = acc[mi][nj][2] + b0;
            float v11 = acc[mi][nj][3] + b1;
            if (MODE == 3) {
                float tr0 = trow[col], tr1 = trow[col + 1];
                v00 = fast_tanh(fmaf(tA, tr0, v00));
                v01 = fast_tanh(fmaf(tA, tr1, v01));
                v10 = fast_tanh(fmaf(tB, tr0, v10));
                v11 = fast_tanh(fmaf(tB, tr1, v11));
            }
            if (MODE == 4) {
                float2 oA = {v00, v01}, oB = {v10, v11};
                *(float2*)(g_OUT + rowA * GOUT + col) = oA;
                *(float2*)(g_OUT + rowB * GOUT + col) = oB;
            } else {
                __nv_bfloat16* Ch = (MODE == 2) ? g_EXh : g_H2h;
                __nv_bfloat16* Cl = (MODE == 2) ? g_EXl : g_H2l;
                __nv_bfloat16 h00 = __float2bfloat16(v00);
                __nv_bfloat16 h01 = __float2bfloat16(v01);
                __nv_bfloat16 h10 = __float2bfloat16(v10);
                __nv_bfloat16 h11 = __float2bfloat16(v11);
                *(__nv_bfloat162*)(Ch + rowA * NTOT + col) = __halves2bfloat162(h00, h01);
                *(__nv_bfloat162*)(Ch + rowB * NTOT + col) = __halves2bfloat162(h10, h11);
                *(__nv_bfloat162*)(Cl + rowA * NTOT + col) = __halves2bfloat162(
                    __float2bfloat16(v00 - __bfloat162float(h00)),
                    __float2bfloat16(v01 - __bfloat162float(h01)));
                *(__nv_bfloat162*)(Cl + rowB * NTOT + col) = __halves2bfloat162(
                    __float2bfloat16(v10 - __bfloat162float(h10)),
                    __float2bfloat16(v11 - __bfloat162float(h11)));
            }
        }
    }
}

// ---------------------------------------------------------------------------
// Reduction
// ---------------------------------------------------------------------------
__global__ void reduce_partial(const float* __restrict__ X,
                               const float* __restrict__ R,
                               const float* __restrict__ stoich,
                               const int* kpp, const int* qpp) {
    __shared__ float w_sh[MBAR];
    __shared__ float red[256];
    int jj = blockIdx.x, t = threadIdx.x;
    int kp = read_int(kpp), qp = read_int(qpp);
    int base = kp * MBAR;
    {
        int m = t;
        const float* xb = X + ((size_t)qp * TOTAL + base + m) * DX;
        bool valid = true;
#pragma unroll
        for (int d = 0; d < DX; d++)
            valid = valid && (xb[d] + stoich[d * MR + jj] >= 0.f);
        size_t rbase = ((size_t)qp * TOTAL + base + m) * MR + jj;
        float rd = R[rbase + MR] - R[rbase];
        w_sh[m] = valid ? rd : 0.f;
    }
    __syncthreads();
    int g = t & 63, c = t >> 6;
    float acc = 0.f;
    for (int mm = c * 64; mm < c * 64 + 64; mm++) {
        float w = w_sh[mm];
        acc += (g_OUT[(size_t)((jj + 1) * MBAR + mm) * GOUT + g]
              - g_OUT[(size_t)mm * GOUT + g]) * w;
    }
    red[t] = acc;
    __syncthreads();
    if (t < 64)
        g_partial[jj * GOUT + t] = red[t] + red[t + 64] + red[t + 128] + red[t + 192];
}

__global__ void final_kernel(float* __restrict__ out) {
    int g = threadIdx.x;
    float acc = 0.f;
#pragma unroll 8
    for (int jj = 0; jj < MR; jj++) acc += g_partial[jj * GOUT + g];
    out[g] = acc;
}

// ---------------------------------------------------------------------------
// Launch
// ---------------------------------------------------------------------------
extern "C" void kernel_launch(void* const* d_in, const int* in_sizes, int n_in,
                              void* d_out, int out_size) {
    const float* X         = (const float*)d_in[0];
    const float* Y         = (const float*)d_in[1];
    const float* R         = (const float*)d_in[2];
    const float* stoich    = (const float*)d_in[3];
    const float* times_t   = (const float*)d_in[4];
    const float* times_tau = (const float*)d_in[5];
    const float* Wx1       = (const float*)d_in[6];
    const float* bx1       = (const float*)d_in[7];
    const float* Wx2       = (const float*)d_in[8];
    const float* bx2       = (const float*)d_in[9];
    const float* Wih       = (const float*)d_in[10];
    const float* Whh       = (const float*)d_in[11];
    const float* bh        = (const float*)d_in[12];
    const float* Wb1       = (const float*)d_in[13];
    const float* bb1       = (const float*)d_in[14];
    const float* Wb2       = (const float*)d_in[15];
    const float* bb2       = (const float*)d_in[16];
    const int*   kptr      = (const int*)d_in[17];
    const int*   kpptr     = (const int*)d_in[18];
    const int*   qptr      = (const int*)d_in[19];
    const int*   qpptr     = (const int*)d_in[20];
    float* out = (float*)d_out;

    // 3-stage smem: stage = 2*A(8KB) + 2*B(BN*64B)
    constexpr int SM23 = 3 * (2 * 128 * 64 + 2 * 256 * 64) + 256;  // 147712
    constexpr int SM4  = 3 * (2 * 128 * 64 + 2 * 64 * 64)  + 256;  // 73984
    cudaFuncSetAttribute(mma_gemm<2, HX, EX_DIM, 256>,
                         cudaFuncAttributeMaxDynamicSharedMemorySize, SM23);
    cudaFuncSetAttribute(mma_gemm<3, EX_DIM, HB, 256>,
                         cudaFuncAttributeMaxDynamicSharedMemorySize, SM23);
    cudaFuncSetAttribute(mma_gemm<4, HB, GOUT, 64>,
                         cudaFuncAttributeMaxDynamicSharedMemorySize, SM4);

    // Weight transpose + hi/lo split (dst arrays selected device-side)
    prep_w<<<dim3(HX / 32, EX_DIM / 32), dim3(32, 8)>>>(Wx2, EX_DIM, 0, 2, HX);
    prep_w<<<dim3(EX_DIM / 32, HB / 32), dim3(32, 8)>>>(Wb1, HB, 1, 3, EX_DIM);
    prep_w<<<dim3(HB / 32, GOUT / 32), dim3(32, 8)>>>(Wb2, GOUT, 0, 4, HB);

    // RNN: 8 fixed step launches; result in g_h0
    rnn_init<<<8, 64>>>();
    for (int s = 0; s < NT - 1; s++)
        rnn_step<<<8, 64>>>(Y, Wih, Whh, bh, kptr, qptr, s);
    bb1eff_kernel<<<HB / 256, 256>>>(Wb1, bb1);

    // H1 via base + delta pre-activations
    pre_h1_kernel<<<MBAR + MR, 256>>>(X, stoich, Wx1, bx1, kpptr, qpptr);
    h1_kernel<<<M_TOTAL / 8, 256>>>();

    mma_gemm<2, HX, EX_DIM, 256><<<dim3(EX_DIM / 256, M_TOTAL / 128), 256, SM23>>>(
        bx2, nullptr, nullptr, nullptr, nullptr);
    mma_gemm<3, EX_DIM, HB, 256><<<dim3(HB / 256, M_TOTAL / 128), 256, SM23>>>(
        nullptr, Wb1, times_t, times_tau, kptr);
    mma_gemm<4, HB, GOUT, 64><<<dim3(1, M_TOTAL / 128), 256, SM4>>>(
        bb2, nullptr, nullptr, nullptr, nullptr);

    reduce_partial<<<MR, 256>>>(X, R, stoich, kpptr, qpptr);
    final_kernel<<<1, GOUT>>>(out);
}